// round 3
// baseline (speedup 1.0000x reference)
#include <cuda_runtime.h>

// Merton jump diffusion, single pass:
//   paths[p,0]   = S0
//   paths[p,t+1] = S0 * exp( sum_{u<=t} drift[u] + CDIFF*zd[u,p] + sqrtJ(nj[u,p])*zj[u,p] )
// nj is tiny Poisson -> sqrt via exact SMEM table. Output transposed via SMEM staging.

#define N_STEPS   2048
#define N_PATHS   32768
#define TPB       64
#define HALF      16                    // pipeline stage = 16 steps
#define N_CHUNKS  (N_STEPS / 32)        // 64 chunks of 32 steps (2 stages each)
#define OUT_COLS  (N_STEPS + 1)
#define JT_SIZE   32

__global__ __launch_bounds__(TPB) void merton_kernel(
    const float* __restrict__ S0p,
    const float* __restrict__ zd,
    const float* __restrict__ zj,
    const int*   __restrict__ njp,
    float*       __restrict__ out)
{
    __shared__ float drift_s[N_STEPS];        // 8 KB
    __shared__ float jtab[JT_SIZE];
    __shared__ float buf[TPB][33];            // 8.4 KB staging, padded

    const int tid   = threadIdx.x;
    const int pbase = blockIdx.x * TPB;
    const int p     = pbase + tid;
    const int wid   = tid >> 5;
    const int lane  = tid & 31;

    const float DT    = 1.0f / 2048.0f;
    const float KAPPA = 0.04602785990f;              // exp(0.045) - 1 (fp32)
    const float CDIFF = 0.2f * 0.02209708691f;       // SIGMA * fl(sqrt(DT)), ref fp32 order

    for (int i = tid; i < N_STEPS; i += TPB) {
        float t   = (float)i * DT;
        float lam = 0.1f + 0.9f * expf(-0.01f * t);
        drift_s[i] = (0.0f - lam * KAPPA) * DT;
    }
    if (tid < JT_SIZE) jtab[tid] = sqrtf((float)tid) * 0.3f;

    const float s0 = S0p[0];
    __syncthreads();

    out[p * OUT_COLS] = s0;                   // column 0 (one-time, negligible)

    // Double-buffered register preload: sets A and B, 16 steps each
    float a1[HALF], a2[HALF];  int a3[HALF];
    float b1[HALF], b2[HALF];  int b3[HALF];

    // Prologue: load stage 0 into A
    #pragma unroll
    for (int s = 0; s < HALF; ++s) {
        const int idx = s * N_PATHS + p;
        a1[s] = __ldcs(zd + idx);
        a2[s] = __ldcs(zj + idx);
        a3[s] = __ldcs(njp + idx);
    }

    float acc = 0.0f;

    for (int c = 0; c < N_CHUNKS; ++c) {
        const int tb = c * 32;

        // Issue loads for second half of this chunk (in flight during computeA)
        #pragma unroll
        for (int s = 0; s < HALF; ++s) {
            const int idx = (tb + HALF + s) * N_PATHS + p;
            b1[s] = __ldcs(zd + idx);
            b2[s] = __ldcs(zj + idx);
            b3[s] = __ldcs(njp + idx);
        }

        // Compute from A -> buf cols [0,16)
        #pragma unroll
        for (int s = 0; s < HALF; ++s) {
            int n = a3[s];  n = (n < JT_SIZE) ? n : (JT_SIZE - 1);
            acc += drift_s[tb + s] + CDIFF * a1[s] + jtab[n] * a2[s];
            buf[tid][s] = s0 * __expf(acc);
        }

        // Issue loads for next chunk's first half (in flight during computeB + drain)
        if (c + 1 < N_CHUNKS) {
            #pragma unroll
            for (int s = 0; s < HALF; ++s) {
                const int idx = (tb + 32 + s) * N_PATHS + p;
                a1[s] = __ldcs(zd + idx);
                a2[s] = __ldcs(zj + idx);
                a3[s] = __ldcs(njp + idx);
            }
        }

        // Compute from B -> buf cols [16,32)
        #pragma unroll
        for (int s = 0; s < HALF; ++s) {
            int n = b3[s];  n = (n < JT_SIZE) ? n : (JT_SIZE - 1);
            acc += drift_s[tb + HALF + s] + CDIFF * b1[s] + jtab[n] * b2[s];
            buf[tid][HALF + s] = s0 * __expf(acc);
        }

        __syncthreads();

        // Drain: 2 warps x 32 rows, 128B coalesced streaming stores
        #pragma unroll
        for (int r = 0; r < 32; ++r) {
            const int row = wid * 32 + r;
            __stcs(&out[(pbase + row) * OUT_COLS + 1 + tb + lane], buf[row][lane]);
        }

        __syncthreads();
    }
}

extern "C" void kernel_launch(void* const* d_in, const int* in_sizes, int n_in,
                              void* d_out, int out_size)
{
    const float* S0 = (const float*)d_in[0];
    const float* zd = (const float*)d_in[1];
    const float* zj = (const float*)d_in[2];
    const int*   nj = (const int*)  d_in[3];
    float*       out = (float*)d_out;

    merton_kernel<<<N_PATHS / TPB, TPB>>>(S0, zd, zj, nj, out);
}

// round 4
// speedup vs baseline: 1.7187x; 1.7187x over previous
#include <cuda_runtime.h>

// Merton jump diffusion, barrier-free per-warp version:
//   paths[p,0]   = S0
//   paths[p,t+1] = S0 * exp( sum_{u<=t} drift[u] + CDIFF*zd[u,p] + sqrtJ(nj[u,p])*zj[u,p] )
// Each warp owns 32 paths; output transpose done in registers via shfl butterfly,
// so there are NO per-chunk __syncthreads and warps run fully decoupled.

#define N_STEPS   2048
#define N_PATHS   32768
#define TPB       128
#define TILE      32
#define N_CHUNKS  (N_STEPS / TILE)
#define OUT_COLS  (N_STEPS + 1)
#define JT_SIZE   32

// In-warp 32x32 transpose: v[j] at lane l is element (row=l, col=j).
// After: v[j] at lane l is element (row=j, col=l). 5 butterfly stages.
__device__ __forceinline__ void warp_transpose32(float (&v)[TILE], int lane) {
    #pragma unroll
    for (int m = 16; m >= 1; m >>= 1) {
        const bool hi = (lane & m);
        #pragma unroll
        for (int j = 0; j < TILE; ++j) {
            if (j & m) continue;                    // handle pair (j, j|m) once
            float send = hi ? v[j] : v[j | m];
            float recv = __shfl_xor_sync(0xffffffffu, send, m);
            if (hi) v[j] = recv; else v[j | m] = recv;
        }
    }
}

__global__ __launch_bounds__(TPB) void merton_kernel(
    const float* __restrict__ S0p,
    const float* __restrict__ zd,
    const float* __restrict__ zj,
    const int*   __restrict__ njp,
    float*       __restrict__ out)
{
    __shared__ float drift_s[N_STEPS];     // 8 KB, broadcast reads only
    __shared__ float jtab[JT_SIZE];

    const int tid   = threadIdx.x;
    const int lane  = tid & 31;
    const int wbase = blockIdx.x * TPB + (tid & ~31);   // warp's first path
    const int p     = wbase + lane;

    const float DT    = 1.0f / 2048.0f;
    const float KAPPA = 0.04602785990f;              // exp(0.045) - 1 (fp32)
    const float CDIFF = 0.2f * 0.02209708691f;       // SIGMA * fl(sqrt(DT)), ref fp32 order

    for (int i = tid; i < N_STEPS; i += TPB) {
        float t   = (float)i * DT;
        float lam = 0.1f + 0.9f * expf(-0.01f * t);
        drift_s[i] = (0.0f - lam * KAPPA) * DT;
    }
    if (tid < JT_SIZE) jtab[tid] = sqrtf((float)tid) * 0.3f;

    const float s0 = S0p[0];
    __syncthreads();                       // one-time: tables ready

    out[p * OUT_COLS] = s0;                // column 0

    // Single register buffer set (R2-style: 96 batched LDGs -> high MLP)
    float r1[TILE], r2[TILE];
    int   r3[TILE];

    #pragma unroll
    for (int s = 0; s < TILE; ++s) {
        const int idx = s * N_PATHS + p;
        r1[s] = __ldcs(zd + idx);
        r2[s] = __ldcs(zj + idx);
        r3[s] = __ldcs(njp + idx);
    }

    float acc = 0.0f;
    float v[TILE];

    for (int c = 0; c < N_CHUNKS; ++c) {
        const int tb = c * TILE;

        // Compute: serial fp32 scan (matches reference order), ex2 off-chain
        #pragma unroll
        for (int s = 0; s < TILE; ++s) {
            int n = r3[s];  n = (n < JT_SIZE) ? n : (JT_SIZE - 1);
            acc += drift_s[tb + s] + CDIFF * r1[s] + jtab[n] * r2[s];
            v[s] = s0 * __expf(acc);
        }

        // Prefetch next chunk NOW; loads fly during transpose + stores
        if (c + 1 < N_CHUNKS) {
            const int nb = (tb + TILE) * N_PATHS + p;
            #pragma unroll
            for (int s = 0; s < TILE; ++s) {
                const int idx = nb + s * N_PATHS;
                r1[s] = __ldcs(zd + idx);
                r2[s] = __ldcs(zj + idx);
                r3[s] = __ldcs(njp + idx);
            }
        }

        // Transpose 32x32 tile in registers (no SMEM, no barriers)
        warp_transpose32(v, lane);

        // Store: v[j] = (path wbase+j, step tb+lane); lanes consecutive -> 128B coalesced
        #pragma unroll
        for (int j = 0; j < TILE; ++j) {
            __stcs(&out[(wbase + j) * OUT_COLS + 1 + tb + lane], v[j]);
        }
    }
}

extern "C" void kernel_launch(void* const* d_in, const int* in_sizes, int n_in,
                              void* d_out, int out_size)
{
    const float* S0 = (const float*)d_in[0];
    const float* zd = (const float*)d_in[1];
    const float* zj = (const float*)d_in[2];
    const int*   nj = (const int*)  d_in[3];
    float*       out = (float*)d_out;

    merton_kernel<<<N_PATHS / TPB, TPB>>>(S0, zd, zj, nj, out);
}